// round 16
// baseline (speedup 1.0000x reference)
#include <cuda_runtime.h>
#include <cuda_bf16.h>
#include <cuda_fp16.h>
#include <cstdint>
#include <math.h>

#define NXc 512
#define NQc 512
#define NUc 128
#define Bc  32768
#define EPSc 1e-3f

// ================= baseline-ISA helpers (compute_103-safe) ==================
__device__ __forceinline__ uint32_t smem_to_u32(const void* p) {
    uint32_t a;
    asm("{ .reg .u64 t; cvta.to.shared.u64 t, %1; cvt.u32.u64 %0, t; }" : "=r"(a) : "l"(p));
    return a;
}
__device__ __forceinline__ void cpasync16(uint32_t d, const void* s) {
    asm volatile("cp.async.cg.shared.global [%0], [%1], 16;" :: "r"(d), "l"(s));
}
#define CP_COMMIT() asm volatile("cp.async.commit_group;" ::: "memory")
#define CP_WAIT(N)  asm volatile("cp.async.wait_group %0;" :: "n"(N) : "memory")

__device__ __forceinline__ void ldsm4(uint32_t* r, uint32_t addr) {
    asm volatile("ldmatrix.sync.aligned.m8n8.x4.shared.b16 {%0,%1,%2,%3}, [%4];"
        : "=r"(r[0]), "=r"(r[1]), "=r"(r[2]), "=r"(r[3]) : "r"(addr));
}
__device__ __forceinline__ void mma16816(float* d, const uint32_t* a, const uint32_t* b) {
    asm volatile("mma.sync.aligned.m16n8k16.row.col.f32.bf16.bf16.f32 "
        "{%0,%1,%2,%3}, {%4,%5,%6,%7}, {%8,%9}, {%0,%1,%2,%3};"
        : "+f"(d[0]), "+f"(d[1]), "+f"(d[2]), "+f"(d[3])
        : "r"(a[0]), "r"(a[1]), "r"(a[2]), "r"(a[3]), "r"(b[0]), "r"(b[1]));
}
__device__ __forceinline__ void mma16816h(float* d, const uint32_t* a, const uint32_t* b) {
    asm volatile("mma.sync.aligned.m16n8k16.row.col.f32.f16.f16.f32 "
        "{%0,%1,%2,%3}, {%4,%5,%6,%7}, {%8,%9}, {%0,%1,%2,%3};"
        : "+f"(d[0]), "+f"(d[1]), "+f"(d[2]), "+f"(d[3])
        : "r"(a[0]), "r"(a[1]), "r"(a[2]), "r"(a[3]), "r"(b[0]), "r"(b[1]));
}
__device__ __forceinline__ uint32_t swz64(uint32_t off) { return off ^ ((off >> 3) & 0x30); }

// ================= scratch (device globals) =================================
__device__ float g_H[1024 * 1024];
__device__ float g_P[NXc * NXc];
__device__ float g_Linv[8 * 64 * 64];
__device__ float g_D11[NQc * NQc];
__device__ float g_RHS[NXc * 1024];
__device__ float g_Z[NXc * 1024];
__device__ float g_S[NXc * 1024];
__device__ unsigned g_barCnt;
// fp16 single planes (activations + weights)
__device__ __half g_xip[(size_t)Bc * NXc];
__device__ __half g_up[(size_t)Bc * NUc];
__device__ __half g_wp[(size_t)Bc * NQc];
__device__ __half g_C1p[NQc * NXc];
__device__ __half g_D11p[NQc * NQc];
__device__ __half g_D12p[NQc * NUc];
__device__ __half g_B2p[NXc * NUc];
__device__ __half g_Sp[NXc * 1024];
// bf16 H path (3-MMA, high precision)
__device__ __nv_bfloat16 g_Xh[1024 * 1024], g_Xl[1024 * 1024];

// ================= misc small kernels =======================================
__device__ __forceinline__ float ftanh(float x) {
    float a = fabsf(x);
    float t = __expf(-2.0f * a);
    float r = __fdividef(1.0f - t, 1.0f + t);
    return copysignf(r, x);
}

// one launch: xi, u -> fp16 single plane; X -> bf16 hi/lo
__global__ void split3(const float* __restrict__ xi, const float* __restrict__ u,
                       const float* __restrict__ X) {
    int blk = blockIdx.x;
    if (blk < 20480) {
        const float* src; __half* dst; int base;
        if (blk < 16384) { src = xi; dst = g_xip; base = blk; }
        else             { src = u;  dst = g_up;  base = blk - 16384; }
        int i = base * 256 + threadIdx.x;
        float4 v = ((const float4*)src)[i];
        __half2 h0, h1;
        h0.x = __float2half_rn(v.x); h0.y = __float2half_rn(v.y);
        h1.x = __float2half_rn(v.z); h1.y = __float2half_rn(v.w);
        ((__half2*)dst)[i * 2] = h0; ((__half2*)dst)[i * 2 + 1] = h1;
    } else {
        int i = (blk - 20480) * 256 + threadIdx.x;
        float4 v = ((const float4*)X)[i];
        __nv_bfloat162 h0, h1, l0, l1;
        h0.x = __float2bfloat16(v.x); h0.y = __float2bfloat16(v.y);
        h1.x = __float2bfloat16(v.z); h1.y = __float2bfloat16(v.w);
        l0.x = __float2bfloat16(v.x - __bfloat162float(h0.x));
        l0.y = __float2bfloat16(v.y - __bfloat162float(h0.y));
        l1.x = __float2bfloat16(v.z - __bfloat162float(h1.x));
        l1.y = __float2bfloat16(v.w - __bfloat162float(h1.y));
        ((__nv_bfloat162*)g_Xh)[i * 2] = h0; ((__nv_bfloat162*)g_Xh)[i * 2 + 1] = h1;
        ((__nv_bfloat162*)g_Xl)[i * 2] = l0; ((__nv_bfloat162*)g_Xl)[i * 2 + 1] = l1;
    }
}

__global__ void prep_mats2(const float* __restrict__ Y1, const float* __restrict__ Chi,
                           const float* __restrict__ D12, const float* __restrict__ B2) {
    int idx = blockIdx.x * 256 + threadIdx.x;
    int i = idx >> 9, j = idx & 511;
    float h1 = g_H[(size_t)i * 1024 + j];
    g_RHS[(size_t)i * 1024 + j] =
        -0.5f * (h1 + ((i == j) ? EPSc : 0.0f) + Y1[(size_t)i * 512 + j] - Y1[(size_t)j * 512 + i]);
    g_RHS[(size_t)i * 1024 + 512 + j] =
        -g_H[(size_t)i * 1024 + 512 + j] - Chi[(size_t)i * 512 + j];
    float rl = 2.0f / (g_H[(size_t)(NXc + i) * 1024 + NXc + i] + EPSc);
    float d = (j < i) ? -g_H[(size_t)(512 + i) * 1024 + 512 + j] * rl : 0.0f;
    g_D11[(size_t)i * 512 + j] = d;
    g_D11p[(size_t)i * 512 + j] = __float2half_rn(d);
    float c1 = Chi[(size_t)j * 512 + i] * rl;
    g_C1p[(size_t)i * 512 + j] = __float2half_rn(c1);
    if (j < NUc) {
        g_D12p[(size_t)i * NUc + j] = __float2half_rn(D12[(size_t)i * NUc + j]);
        g_B2p[(size_t)i * NUc + j]  = __float2half_rn(B2[(size_t)i * NUc + j]);
    }
}

__global__ void reset_bar() { if (threadIdx.x == 0) g_barCnt = 0u; }

// ================= solver device pieces (fp32, 256 threads) =================
__device__ __forceinline__ void gbar(unsigned& gen) {
    __syncthreads();
    gen += 16;
    if (threadIdx.x == 0) {
        __threadfence();
        atomicAdd(&g_barCnt, 1u);
        while (*(volatile unsigned*)&g_barCnt < gen) { }
        __threadfence();
    }
    __syncthreads();
}

__device__ void dev_potf2_inv(int k, float (*S)[65], float* Dinv, float* sdp)
{
    int tid = threadIdx.x;
    for (int idx = tid; idx < 4096; idx += 256) {
        int i = idx >> 6, j = idx & 63;
        S[i][j] = g_P[(size_t)(k * 64 + i) * NXc + k * 64 + j];
    }
    __syncthreads();
    for (int j = 0; j < 64; ++j) {
        if (tid == 0) *sdp = rsqrtf(S[j][j]);
        __syncthreads();
        if (tid >= j && tid < 64) S[tid][j] *= *sdp;
        __syncthreads();
        for (int idx = tid; idx < 4096; idx += 256) {
            int i = idx >> 6, c = idx & 63;
            if (i > j && c > j) S[i][c] -= S[i][j] * S[c][j];
        }
        __syncthreads();
    }
    if (tid < 64) Dinv[tid] = 1.0f / S[tid][tid];
    __syncthreads();
    int wd = tid >> 5, lane = tid & 31;
    for (int cc = 0; cc < 8; ++cc) {
        int c = wd * 8 + cc;
        float x0 = (lane == c) ? 1.0f : 0.0f;
        float x1 = (lane + 32 == c) ? 1.0f : 0.0f;
        for (int i = c; i < 64; ++i) {
            float src = (i < 32) ? x0 : x1;
            float part = __shfl_sync(0xffffffffu, src, i & 31);
            float xv = part * Dinv[i];
            if (i < 32) { if (lane == i) x0 = xv; }
            else        { if (lane == i - 32) x1 = xv; }
            if (lane > i)      x0 -= S[lane][i] * xv;
            if (lane + 32 > i) x1 -= S[lane + 32][i] * xv;
        }
        g_Linv[k * 4096 + lane * 64 + c] = x0;
        g_Linv[k * 4096 + (lane + 32) * 64 + c] = x1;
    }
}

__device__ void dev_gemm_ABtK(const float* A, int lda, const float* B, int ldb,
                              float* C, int ldc, int K,
                              float alpha, float beta, float diagAdd,
                              float (*As)[68], float (*Bs)[68])
{
    int tid = threadIdx.x;
    int tx = tid & 15, ty = tid >> 4;
    float acc[4][4] = {};
    for (int kt = 0; kt < K; kt += 16) {
        __syncthreads();
        {
            int r = tid >> 2, kq = (tid & 3) * 4;
            float4 v = *(const float4*)(A + (size_t)r * lda + kt + kq);
            As[kq + 0][r] = v.x; As[kq + 1][r] = v.y; As[kq + 2][r] = v.z; As[kq + 3][r] = v.w;
            float4 w = *(const float4*)(B + (size_t)r * ldb + kt + kq);
            Bs[kq + 0][r] = w.x; Bs[kq + 1][r] = w.y; Bs[kq + 2][r] = w.z; Bs[kq + 3][r] = w.w;
        }
        __syncthreads();
        #pragma unroll
        for (int kk = 0; kk < 16; ++kk) {
            float4 a = *(const float4*)&As[kk][ty * 4];
            float4 b = *(const float4*)&Bs[kk][tx * 4];
            float am[4] = {a.x, a.y, a.z, a.w};
            float bm[4] = {b.x, b.y, b.z, b.w};
            #pragma unroll
            for (int i = 0; i < 4; ++i)
                #pragma unroll
                for (int j = 0; j < 4; ++j)
                    acc[i][j] += am[i] * bm[j];
        }
    }
    __syncthreads();
    #pragma unroll
    for (int i = 0; i < 4; ++i)
        #pragma unroll
        for (int j = 0; j < 4; ++j) {
            int li = ty * 4 + i, lj = tx * 4 + j;
            float v = alpha * acc[i][j];
            if (beta != 0.0f) v += beta * C[(size_t)li * ldc + lj];
            if (li == lj) v += diagAdd;
            C[(size_t)li * ldc + lj] = v;
        }
}

__device__ void dev_fwd(int c0, float (*Lt)[65], float (*Zt)[65])
{
    int tid = threadIdx.x;
    int tx = tid & 15, ty = tid >> 4;
    for (int ib = 0; ib < 8; ++ib) {
        float acc[4][4] = {};
        for (int jb = 0; jb < ib; ++jb) {
            for (int idx = tid; idx < 4096; idx += 256) {
                int i = idx >> 6, j = idx & 63;
                Lt[i][j] = g_P[(size_t)(ib * 64 + i) * 512 + jb * 64 + j];
                Zt[i][j] = g_Z[(size_t)(jb * 64 + i) * 1024 + c0 + j];
            }
            __syncthreads();
            #pragma unroll 8
            for (int kk = 0; kk < 64; ++kk)
                #pragma unroll
                for (int ii = 0; ii < 4; ++ii)
                    #pragma unroll
                    for (int jj = 0; jj < 4; ++jj)
                        acc[ii][jj] += Lt[ty * 4 + ii][kk] * Zt[kk][tx * 4 + jj];
            __syncthreads();
        }
        #pragma unroll
        for (int ii = 0; ii < 4; ++ii)
            #pragma unroll
            for (int jj = 0; jj < 4; ++jj)
                Zt[ty * 4 + ii][tx * 4 + jj] =
                    g_RHS[(size_t)(ib * 64 + ty * 4 + ii) * 1024 + c0 + tx * 4 + jj] - acc[ii][jj];
        for (int idx = tid; idx < 4096; idx += 256) {
            int i = idx >> 6, j = idx & 63;
            Lt[i][j] = g_Linv[ib * 4096 + i * 64 + j];
        }
        __syncthreads();
        float z[4][4] = {};
        #pragma unroll 8
        for (int kk = 0; kk < 64; ++kk)
            #pragma unroll
            for (int ii = 0; ii < 4; ++ii)
                #pragma unroll
                for (int jj = 0; jj < 4; ++jj)
                    z[ii][jj] += Lt[ty * 4 + ii][kk] * Zt[kk][tx * 4 + jj];
        #pragma unroll
        for (int ii = 0; ii < 4; ++ii)
            #pragma unroll
            for (int jj = 0; jj < 4; ++jj)
                g_Z[(size_t)(ib * 64 + ty * 4 + ii) * 1024 + c0 + tx * 4 + jj] = z[ii][jj];
        __syncthreads();
    }
}

__device__ void dev_bwd(int c0, float (*Lt)[65], float (*Zt)[65])
{
    int tid = threadIdx.x;
    int tx = tid & 15, ty = tid >> 4;
    for (int ib = 7; ib >= 0; --ib) {
        float acc[4][4] = {};
        for (int jb = ib + 1; jb < 8; ++jb) {
            for (int idx = tid; idx < 4096; idx += 256) {
                int i = idx >> 6, j = idx & 63;
                Lt[i][j] = g_P[(size_t)(jb * 64 + i) * 512 + ib * 64 + j];
                Zt[i][j] = g_S[(size_t)(jb * 64 + i) * 1024 + c0 + j];
            }
            __syncthreads();
            #pragma unroll 8
            for (int kk = 0; kk < 64; ++kk)
                #pragma unroll
                for (int ii = 0; ii < 4; ++ii)
                    #pragma unroll
                    for (int jj = 0; jj < 4; ++jj)
                        acc[ii][jj] += Lt[kk][ty * 4 + ii] * Zt[kk][tx * 4 + jj];
            __syncthreads();
        }
        #pragma unroll
        for (int ii = 0; ii < 4; ++ii)
            #pragma unroll
            for (int jj = 0; jj < 4; ++jj)
                Zt[ty * 4 + ii][tx * 4 + jj] =
                    g_Z[(size_t)(ib * 64 + ty * 4 + ii) * 1024 + c0 + tx * 4 + jj] - acc[ii][jj];
        for (int idx = tid; idx < 4096; idx += 256) {
            int i = idx >> 6, j = idx & 63;
            Lt[i][j] = g_Linv[ib * 4096 + i * 64 + j];
        }
        __syncthreads();
        float z[4][4] = {};
        #pragma unroll 8
        for (int kk = 0; kk < 64; ++kk)
            #pragma unroll
            for (int ii = 0; ii < 4; ++ii)
                #pragma unroll
                for (int jj = 0; jj < 4; ++jj)
                    z[ii][jj] += Lt[kk][ty * 4 + ii] * Zt[kk][tx * 4 + jj];
        #pragma unroll
        for (int ii = 0; ii < 4; ++ii)
            #pragma unroll
            for (int jj = 0; jj < 4; ++jj)
                g_S[(size_t)(ib * 64 + ty * 4 + ii) * 1024 + c0 + tx * 4 + jj] = z[ii][jj];
        __syncthreads();
    }
}

// ================= bf16 3-MMA GEMM (H only) =================================
struct Seg {
    const __nv_bfloat16 *Ah, *Al, *Wh, *Wl;
    int lda, ldw, K;
};

template <int NT>
__global__ __launch_bounds__(512, 2) void mma_gemm(
    Seg s0, Seg s1, Seg s2, float* __restrict__ C, int ldc, int addTo)
{
    extern __shared__ __align__(128) char smem[];
    constexpr int AP  = 128 * 64;
    constexpr int WP  = NT * 64;
    constexpr int STG = 2 * AP + 2 * WP;
    constexpr int NAw = NT / 32;

    uint32_t sb = smem_to_u32(smem);
    int tid = threadIdx.x;
    int wid = tid >> 5, lane = tid & 31;
    int m0 = blockIdx.y * 128, n0 = blockIdx.x * NT;
    int wm = (wid & 3) * 32;
    int wn = (wid >> 2) * (NT / 4);

    int nk0 = s0.K >> 5, nk1 = s1.K >> 5, nk2 = s2.K >> 5;
    int nk = nk0 + nk1 + nk2;

    auto issue = [&](int c) {
        int cs = c;
        const Seg* sg = &s0;
        if (cs >= nk0) { cs -= nk0; sg = &s1; if (cs >= nk1) { cs -= nk1; sg = &s2; } }
        int kt = cs << 5;
        uint32_t stu = sb + (c & 1) * STG;
        #pragma unroll
        for (int s = tid; s < 1024; s += 512) {
            int pl = s >> 9, rem = s & 511, row = rem >> 2, q = rem & 3;
            const __nv_bfloat16* src =
                (pl ? sg->Al : sg->Ah) + (size_t)(m0 + row) * sg->lda + kt + q * 8;
            cpasync16(stu + pl * AP + swz64(row * 64 + q * 16), src);
        }
        #pragma unroll
        for (int s = tid; s < NT * 8; s += 512) {
            int pl = (s >= NT * 4) ? 1 : 0;
            int rem = pl ? s - NT * 4 : s;
            int row = rem >> 2, q = rem & 3;
            const __nv_bfloat16* src =
                (pl ? sg->Wl : sg->Wh) + (size_t)(n0 + row) * sg->ldw + kt + q * 8;
            cpasync16(stu + 2 * AP + pl * WP + swz64(row * 64 + q * 16), src);
        }
        CP_COMMIT();
    };

    float acc[2][NAw][4] = {};

    issue(0);
    for (int c = 0; c < nk; ++c) {
        if (c + 1 < nk) { issue(c + 1); CP_WAIT(1); }
        else            { CP_WAIT(0); }
        __syncthreads();
        uint32_t stu = sb + (c & 1) * STG;
        #pragma unroll
        for (int ks = 0; ks < 2; ++ks) {
            uint32_t ah[2][4], al[2][4];
            #pragma unroll
            for (int am = 0; am < 2; ++am) {
                uint32_t off = (uint32_t)(wm + am * 16 + (lane & 15)) * 64
                               + ks * 32 + (lane >> 4) * 16;
                ldsm4(ah[am], stu + swz64(off));
                ldsm4(al[am], stu + AP + swz64(off));
            }
            #pragma unroll
            for (int p = 0; p < NAw / 2; ++p) {
                int g = lane >> 3;
                uint32_t off = (uint32_t)(wn + p * 16 + ((g >> 1) << 3) + (lane & 7)) * 64
                               + ks * 32 + (g & 1) * 16;
                uint32_t th[4], tl[4];
                ldsm4(th, stu + 2 * AP + swz64(off));
                ldsm4(tl, stu + 2 * AP + WP + swz64(off));
                #pragma unroll
                for (int am = 0; am < 2; ++am) {
                    mma16816(acc[am][2 * p],     ah[am], th);
                    mma16816(acc[am][2 * p],     ah[am], tl);
                    mma16816(acc[am][2 * p],     al[am], th);
                    mma16816(acc[am][2 * p + 1], ah[am], th + 2);
                    mma16816(acc[am][2 * p + 1], ah[am], tl + 2);
                    mma16816(acc[am][2 * p + 1], al[am], th + 2);
                }
            }
        }
        __syncthreads();
    }

    #pragma unroll
    for (int am = 0; am < 2; ++am) {
        int r0 = m0 + wm + am * 16 + (lane >> 2);
        #pragma unroll
        for (int j = 0; j < NAw; ++j) {
            int cc = n0 + wn + j * 8 + (lane & 3) * 2;
            float* p0 = C + (size_t)r0 * ldc + cc;
            float* p1 = C + (size_t)(r0 + 8) * ldc + cc;
            float2 v0 = make_float2(acc[am][j][0], acc[am][j][1]);
            float2 v1 = make_float2(acc[am][j][2], acc[am][j][3]);
            if (addTo) {
                float2 o0 = *(const float2*)p0, o1 = *(const float2*)p1;
                v0.x += o0.x; v0.y += o0.y; v1.x += o1.x; v1.y += o1.y;
            }
            *(float2*)p0 = v0;
            *(float2*)p1 = v1;
        }
    }
}

// ================= fp16 single-MMA GEMM (out) ===============================
struct Seg3 {
    const __half *Ap, *Wp;
    int lda, ldw, K;
};

__global__ __launch_bounds__(512, 2) void mma_gemm_h(
    Seg3 s0, Seg3 s1, Seg3 s2, float* __restrict__ C, int ldc)
{
    extern __shared__ __align__(128) char smem[];
    constexpr int AP  = 128 * 64;   // single A plane per stage
    constexpr int WP  = 128 * 64;   // single W plane per stage
    constexpr int STG = AP + WP;

    uint32_t sb = smem_to_u32(smem);
    int tid = threadIdx.x;
    int wid = tid >> 5, lane = tid & 31;
    int m0 = blockIdx.y * 128, n0 = blockIdx.x * 128;
    int wm = (wid & 3) * 32;
    int wn = (wid >> 2) * 32;

    int nk0 = s0.K >> 5, nk1 = s1.K >> 5, nk2 = s2.K >> 5;
    int nk = nk0 + nk1 + nk2;

    auto issue = [&](int c) {
        int cs = c;
        const Seg3* sg = &s0;
        if (cs >= nk0) { cs -= nk0; sg = &s1; if (cs >= nk1) { cs -= nk1; sg = &s2; } }
        int kt = cs << 5;
        uint32_t stu = sb + (c & 1) * STG;
        {
            int s = tid;   // 512 A items, one per thread
            int row = s >> 2, q = s & 3;
            const __half* src = sg->Ap + (size_t)(m0 + row) * sg->lda + kt + q * 8;
            cpasync16(stu + swz64(row * 64 + q * 16), src);
        }
        {
            int s = tid;   // 512 W items, one per thread
            int row = s >> 2, q = s & 3;
            const __half* src = sg->Wp + (size_t)(n0 + row) * sg->ldw + kt + q * 8;
            cpasync16(stu + AP + swz64(row * 64 + q * 16), src);
        }
        CP_COMMIT();
    };

    float acc[2][4][4] = {};

    issue(0);
    for (int c = 0; c < nk; ++c) {
        if (c + 1 < nk) { issue(c + 1); CP_WAIT(1); }
        else            { CP_WAIT(0); }
        __syncthreads();
        uint32_t stu = sb + (c & 1) * STG;
        #pragma unroll
        for (int ks = 0; ks < 2; ++ks) {
            uint32_t ah[2][4];
            #pragma unroll
            for (int am = 0; am < 2; ++am) {
                uint32_t off = (uint32_t)(wm + am * 16 + (lane & 15)) * 64
                               + ks * 32 + (lane >> 4) * 16;
                ldsm4(ah[am], stu + swz64(off));
            }
            #pragma unroll
            for (int p = 0; p < 2; ++p) {
                int g = lane >> 3;
                uint32_t off = (uint32_t)(wn + p * 16 + ((g >> 1) << 3) + (lane & 7)) * 64
                               + ks * 32 + (g & 1) * 16;
                uint32_t th[4];
                ldsm4(th, stu + AP + swz64(off));
                #pragma unroll
                for (int am = 0; am < 2; ++am) {
                    mma16816h(acc[am][2 * p],     ah[am], th);
                    mma16816h(acc[am][2 * p + 1], ah[am], th + 2);
                }
            }
        }
        __syncthreads();
    }

    #pragma unroll
    for (int am = 0; am < 2; ++am) {
        int r0 = m0 + wm + am * 16 + (lane >> 2);
        #pragma unroll
        for (int j = 0; j < 4; ++j) {
            int cc = n0 + wn + j * 8 + (lane & 3) * 2;
            *(float2*)(C + (size_t)r0 * ldc + cc) =
                make_float2(acc[am][j][0], acc[am][j][1]);
            *(float2*)(C + (size_t)(r0 + 8) * ldc + cc) =
                make_float2(acc[am][j][2], acc[am][j][3]);
        }
    }
}

// ============= fused base+cross GEMM (fp16 1-MMA) + scan + solver ===========
__global__ __launch_bounds__(256) void scan_solve(const float* __restrict__ Pstar)
{
    extern __shared__ __align__(128) char smem[];
    int tid = threadIdx.x;

    if (blockIdx.x < 16) {
        float (*shA)[68] = (float(*)[68])(smem);
        float (*shB)[68] = (float(*)[68])(smem + 16 * 68 * 4);
        float (*S64)[65] = (float(*)[65])(smem + 2 * 16 * 68 * 4);
        float (*T64)[65] = (float(*)[65])(smem + 2 * 16 * 68 * 4 + 64 * 65 * 4);
        float* Dinv      = (float*)(smem + 2 * 16 * 68 * 4 + 2 * 64 * 65 * 4);
        float* sdv       = Dinv + 64;
        int cta = blockIdx.x;
        unsigned gen = 0;

        {
            int t = 0;
            for (int i = 0; i < 8; ++i)
                for (int j = 0; j <= i; ++j, ++t)
                    if ((t & 15) == cta)
                        dev_gemm_ABtK(Pstar + (size_t)i * 64 * 512, 512,
                                      Pstar + (size_t)j * 64 * 512, 512,
                                      g_P + (size_t)i * 64 * 512 + j * 64, 512,
                                      512, 0.5f, 0.0f, (i == j) ? EPSc : 0.0f,
                                      shA, shB);
            gbar(gen);
        }

        for (int k = 0; k < 8; ++k) {
            if (cta == 0) dev_potf2_inv(k, S64, Dinv, sdv);
            gbar(gen);
            int nrem = 7 - k;
            if (nrem > 0) {
                if (cta < nrem) {
                    int i = k + 1 + cta;
                    float* panel = g_P + (size_t)i * 64 * 512 + k * 64;
                    dev_gemm_ABtK(panel, 512, g_Linv + k * 4096, 64,
                                  panel, 512, 64, 1.0f, 0.0f, 0.0f, shA, shB);
                }
                gbar(gen);
                int t = 0;
                for (int i = k + 1; i < 8; ++i)
                    for (int j = k + 1; j <= i; ++j, ++t)
                        if ((t & 15) == cta)
                            dev_gemm_ABtK(g_P + (size_t)i * 64 * 512 + k * 64, 512,
                                          g_P + (size_t)j * 64 * 512 + k * 64, 512,
                                          g_P + (size_t)i * 64 * 512 + j * 64, 512,
                                          64, -1.0f, 1.0f, 0.0f, shA, shB);
                gbar(gen);
            }
        }
        dev_fwd(cta * 64, S64, T64);
        dev_bwd(cta * 64, S64, T64);
        gbar(gen);
        for (int i = cta * 256 + tid; i < NXc * 1024 / 4; i += 4096) {
            float4 v = ((const float4*)g_S)[i];
            __half2 h0, h1;
            h0.x = __float2half_rn(v.x); h0.y = __float2half_rn(v.y);
            h1.x = __float2half_rn(v.z); h1.y = __float2half_rn(v.w);
            ((__half2*)g_Sp)[i * 2] = h0; ((__half2*)g_Sp)[i * 2 + 1] = h1;
        }
        return;
    }

    constexpr int APc  = 128 * 64;            // single A plane stage
    constexpr int WPc  = 64 * 64;             // single W plane stage
    constexpr int STGc = APc + WPc;           // 12288
    constexpr int CRo  = 2 * STGc;            // 24576
    constexpr int DSo  = CRo + 128 * 68 * 4;  // 59392
    uint32_t sb = smem_to_u32(smem);
    float* cross = (float*)(smem + CRo);
    float* ds    = (float*)(smem + DSo);
    int wid = tid >> 5, lane = tid & 31;
    int strip0 = (blockIdx.x - 16) * 128;

    const __half* xiP = g_xip + (size_t)strip0 * NXc;
    const __half* uP  = g_up  + (size_t)strip0 * NUc;
    const __half* wP  = g_wp  + (size_t)strip0 * NQc;

    for (int b = 0; b < 8; ++b) {
        int nk = 20 + 2 * b;

        auto issue = [&](int c) {
            int cs = c;
            const __half *Ap, *Wp;
            int lda, ldw;
            if (cs < 16) {
                Ap = xiP; lda = NXc;
                Wp = g_C1p + (size_t)b * 64 * NXc; ldw = NXc;
            } else if (cs < 20) {
                cs -= 16;
                Ap = uP; lda = NUc;
                Wp = g_D12p + (size_t)b * 64 * NUc; ldw = NUc;
            } else {
                cs -= 20;
                Ap = wP; lda = NQc;
                Wp = g_D11p + (size_t)b * 64 * NQc; ldw = NQc;
            }
            int kt = cs << 5;
            uint32_t stu = sb + (c & 1) * STGc;
            #pragma unroll
            for (int s = tid; s < 512; s += 256) {
                int row = s >> 2, q = s & 3;
                const __half* src = Ap + (size_t)row * lda + kt + q * 8;
                cpasync16(stu + swz64(row * 64 + q * 16), src);
            }
            {
                int s = tid;   // 256 W items, one per thread
                int row = s >> 2, q = s & 3;
                const __half* src = Wp + (size_t)row * ldw + kt + q * 8;
                cpasync16(stu + APc + swz64(row * 64 + q * 16), src);
            }
            CP_COMMIT();
        };

        float acc[2][4][4] = {};
        int wm = (wid & 3) * 32;
        int wn = (wid >> 2) * 32;

        issue(0);
        for (int c = 0; c < nk; ++c) {
            if (c + 1 < nk) { issue(c + 1); CP_WAIT(1); }
            else            { CP_WAIT(0); }
            __syncthreads();
            uint32_t stu = sb + (c & 1) * STGc;
            #pragma unroll
            for (int ks = 0; ks < 2; ++ks) {
                uint32_t ah[2][4];
                #pragma unroll
                for (int am = 0; am < 2; ++am) {
                    uint32_t off = (uint32_t)(wm + am * 16 + (lane & 15)) * 64
                                   + ks * 32 + (lane >> 4) * 16;
                    ldsm4(ah[am], stu + swz64(off));
                }
                #pragma unroll
                for (int p = 0; p < 2; ++p) {
                    int g = lane >> 3;
                    uint32_t off = (uint32_t)(wn + p * 16 + ((g >> 1) << 3) + (lane & 7)) * 64
                                   + ks * 32 + (g & 1) * 16;
                    uint32_t th[4];
                    ldsm4(th, stu + APc + swz64(off));
                    #pragma unroll
                    for (int am = 0; am < 2; ++am) {
                        mma16816h(acc[am][2 * p],     ah[am], th);
                        mma16816h(acc[am][2 * p + 1], ah[am], th + 2);
                    }
                }
            }
            __syncthreads();
        }

        #pragma unroll
        for (int am = 0; am < 2; ++am) {
            int r0 = wm + am * 16 + (lane >> 2);
            #pragma unroll
            for (int j = 0; j < 4; ++j) {
                int cc = wn + j * 8 + (lane & 3) * 2;
                cross[r0 * 68 + cc]           = acc[am][j][0];
                cross[r0 * 68 + cc + 1]       = acc[am][j][1];
                cross[(r0 + 8) * 68 + cc]     = acc[am][j][2];
                cross[(r0 + 8) * 68 + cc + 1] = acc[am][j][3];
            }
        }
        for (int idx = tid; idx < 4096; idx += 256) {
            int i = idx >> 6, j = idx & 63;
            ds[i * 65 + j] = g_D11[(size_t)(b * 64 + i) * NQc + b * 64 + j];
        }
        __syncthreads();

        if (tid < 128) {
            int r = strip0 + tid;
            float bb[64];
            #pragma unroll
            for (int q = 0; q < 64; ++q) bb[q] = cross[tid * 68 + q];
            float wv[64];
            #pragma unroll
            for (int i = 0; i < 64; ++i) {
                float s0 = 0.f, s1 = 0.f, s2 = 0.f, s3 = 0.f;
                #pragma unroll
                for (int j = 0; j < 64; ++j) {
                    if (j < i) {
                        float p = wv[j] * ds[i * 65 + j];
                        if      ((j & 3) == 0) s0 += p;
                        else if ((j & 3) == 1) s1 += p;
                        else if ((j & 3) == 2) s2 += p;
                        else                   s3 += p;
                    }
                }
                wv[i] = ftanh(bb[i] + ((s0 + s1) + (s2 + s3)));
            }
            __half2* wpp = (__half2*)(g_wp + (size_t)r * NQc + b * 64);
            #pragma unroll
            for (int q = 0; q < 32; ++q) {
                __half2 h;
                h.x = __float2half_rn(wv[q * 2]); h.y = __float2half_rn(wv[q * 2 + 1]);
                wpp[q] = h;
            }
        }
        __syncthreads();
    }
}

// ================= host orchestration =======================================
extern "C" void kernel_launch(void* const* d_in, const int* in_sizes, int n_in,
                              void* d_out, int out_size)
{
    const float* xi    = (const float*)d_in[1];
    const float* u     = (const float*)d_in[2];
    const float* Pstar = (const float*)d_in[3];
    const float* Chi   = (const float*)d_in[4];
    const float* Y1    = (const float*)d_in[5];
    const float* B2    = (const float*)d_in[6];
    const float* D12   = (const float*)d_in[7];
    const float* X     = (const float*)d_in[8];
    float* out = (float*)d_out;

    float* H;
    __half *xip, *up, *wp, *Sp, *B2p;
    __nv_bfloat16 *Xh, *Xl;
    cudaGetSymbolAddress((void**)&H, g_H);
    cudaGetSymbolAddress((void**)&xip, g_xip);
    cudaGetSymbolAddress((void**)&up, g_up);
    cudaGetSymbolAddress((void**)&wp, g_wp);
    cudaGetSymbolAddress((void**)&Xh, g_Xh);
    cudaGetSymbolAddress((void**)&Xl, g_Xl);
    cudaGetSymbolAddress((void**)&Sp, g_Sp);
    cudaGetSymbolAddress((void**)&B2p, g_B2p);

    constexpr int SM64  = 2 * (2 * 128 * 64 + 2 * 64 * 64);  // 49152 (bf16 H)
    constexpr int SMH   = 2 * (128 * 64 + 128 * 64);         // 32768 (fp16 out)
    constexpr int SMSF  = 2 * (128 * 64 + 64 * 64) + 128 * 68 * 4 + 64 * 65 * 4; // 76032
    cudaFuncSetAttribute(mma_gemm<64>, cudaFuncAttributeMaxDynamicSharedMemorySize, SM64);
    cudaFuncSetAttribute(mma_gemm_h,   cudaFuncAttributeMaxDynamicSharedMemorySize, SMH);
    cudaFuncSetAttribute(scan_solve,   cudaFuncAttributeMaxDynamicSharedMemorySize, SMSF);

    Seg zs = { nullptr, nullptr, nullptr, nullptr, 0, 0, 0 };

    // one launch: xi/u -> fp16 plane; X -> bf16 hi/lo
    split3<<<21504, 256>>>(xi, u, X);

    // H = X X^T via bf16 3-MMA (high precision, feeds inverse chain)
    Seg sXX = { Xh, Xl, Xh, Xl, 1024, 1024, 1024 };
    mma_gemm<64><<<dim3(16, 8), 512, SM64>>>(sXX, zs, zs, H, 1024, 0);

    // prep (RHS, D11(+fp16 plane), C1/D12/B2 fp16 planes)
    prep_mats2<<<1024, 256>>>(Y1, Chi, D12, B2);

    // fused: solver (16 CTAs: P + Cholesky + solves) || base+cross GEMM + scan
    reset_bar<<<1, 32>>>();
    scan_solve<<<272, 256, SMSF>>>(Pstar);

    // out = xi A^T + w B1^T + u B2^T  (fp16 single-MMA)
    Seg3 sXA = { xip, Sp, NXc, 1024, NXc };
    Seg3 sWB = { wp, Sp + 512, NQc, 1024, NQc };
    Seg3 sUB = { up, B2p, NUc, NUc, NUc };
    mma_gemm_h<<<dim3(4, 256), 512, SMH>>>(sXA, sWB, sUB, out, NXc);
}

// round 17
// speedup vs baseline: 1.0291x; 1.0291x over previous
#include <cuda_runtime.h>
#include <cuda_bf16.h>
#include <cuda_fp16.h>
#include <cstdint>
#include <math.h>

#define NXc 512
#define NQc 512
#define NUc 128
#define Bc  32768
#define EPSc 1e-3f

// ================= baseline-ISA helpers (compute_103-safe) ==================
__device__ __forceinline__ uint32_t smem_to_u32(const void* p) {
    uint32_t a;
    asm("{ .reg .u64 t; cvta.to.shared.u64 t, %1; cvt.u32.u64 %0, t; }" : "=r"(a) : "l"(p));
    return a;
}
__device__ __forceinline__ void cpasync16(uint32_t d, const void* s) {
    asm volatile("cp.async.cg.shared.global [%0], [%1], 16;" :: "r"(d), "l"(s));
}
#define CP_COMMIT() asm volatile("cp.async.commit_group;" ::: "memory")
#define CP_WAIT(N)  asm volatile("cp.async.wait_group %0;" :: "n"(N) : "memory")

__device__ __forceinline__ void ldsm4(uint32_t* r, uint32_t addr) {
    asm volatile("ldmatrix.sync.aligned.m8n8.x4.shared.b16 {%0,%1,%2,%3}, [%4];"
        : "=r"(r[0]), "=r"(r[1]), "=r"(r[2]), "=r"(r[3]) : "r"(addr));
}
__device__ __forceinline__ void mma16816(float* d, const uint32_t* a, const uint32_t* b) {
    asm volatile("mma.sync.aligned.m16n8k16.row.col.f32.bf16.bf16.f32 "
        "{%0,%1,%2,%3}, {%4,%5,%6,%7}, {%8,%9}, {%0,%1,%2,%3};"
        : "+f"(d[0]), "+f"(d[1]), "+f"(d[2]), "+f"(d[3])
        : "r"(a[0]), "r"(a[1]), "r"(a[2]), "r"(a[3]), "r"(b[0]), "r"(b[1]));
}
__device__ __forceinline__ void mma16816h(float* d, const uint32_t* a, const uint32_t* b) {
    asm volatile("mma.sync.aligned.m16n8k16.row.col.f32.f16.f16.f32 "
        "{%0,%1,%2,%3}, {%4,%5,%6,%7}, {%8,%9}, {%0,%1,%2,%3};"
        : "+f"(d[0]), "+f"(d[1]), "+f"(d[2]), "+f"(d[3])
        : "r"(a[0]), "r"(a[1]), "r"(a[2]), "r"(a[3]), "r"(b[0]), "r"(b[1]));
}
__device__ __forceinline__ uint32_t swz64(uint32_t off)  { return off ^ ((off >> 3) & 0x30); }
__device__ __forceinline__ uint32_t swz128(uint32_t off) { return off ^ ((off >> 3) & 0x70); }

// ================= scratch (device globals) =================================
__device__ float g_H[1024 * 1024];
__device__ float g_P[NXc * NXc];
__device__ float g_Linv[8 * 64 * 64];
__device__ float g_D11[NQc * NQc];
__device__ float g_RHS[NXc * 1024];
__device__ float g_Z[NXc * 1024];
__device__ float g_S[NXc * 1024];
__device__ unsigned g_barCnt;
// fp16 single planes (activations + weights)
__device__ __half g_xip[(size_t)Bc * NXc];
__device__ __half g_up[(size_t)Bc * NUc];
__device__ __half g_wp[(size_t)Bc * NQc];
__device__ __half g_C1p[NQc * NXc];
__device__ __half g_D11p[NQc * NQc];
__device__ __half g_D12p[NQc * NUc];
__device__ __half g_B2p[NXc * NUc];
__device__ __half g_Sp[NXc * 1024];
// bf16 H path (3-MMA, high precision)
__device__ __nv_bfloat16 g_Xh[1024 * 1024], g_Xl[1024 * 1024];

// ================= misc small kernels =======================================
__device__ __forceinline__ float ftanh(float x) {
    float a = fabsf(x);
    float t = __expf(-2.0f * a);
    float r = __fdividef(1.0f - t, 1.0f + t);
    return copysignf(r, x);
}

// one launch: xi, u -> fp16 single plane; X -> bf16 hi/lo
__global__ void split3(const float* __restrict__ xi, const float* __restrict__ u,
                       const float* __restrict__ X) {
    int blk = blockIdx.x;
    if (blk < 20480) {
        const float* src; __half* dst; int base;
        if (blk < 16384) { src = xi; dst = g_xip; base = blk; }
        else             { src = u;  dst = g_up;  base = blk - 16384; }
        int i = base * 256 + threadIdx.x;
        float4 v = ((const float4*)src)[i];
        __half2 h0, h1;
        h0.x = __float2half_rn(v.x); h0.y = __float2half_rn(v.y);
        h1.x = __float2half_rn(v.z); h1.y = __float2half_rn(v.w);
        ((__half2*)dst)[i * 2] = h0; ((__half2*)dst)[i * 2 + 1] = h1;
    } else {
        int i = (blk - 20480) * 256 + threadIdx.x;
        float4 v = ((const float4*)X)[i];
        __nv_bfloat162 h0, h1, l0, l1;
        h0.x = __float2bfloat16(v.x); h0.y = __float2bfloat16(v.y);
        h1.x = __float2bfloat16(v.z); h1.y = __float2bfloat16(v.w);
        l0.x = __float2bfloat16(v.x - __bfloat162float(h0.x));
        l0.y = __float2bfloat16(v.y - __bfloat162float(h0.y));
        l1.x = __float2bfloat16(v.z - __bfloat162float(h1.x));
        l1.y = __float2bfloat16(v.w - __bfloat162float(h1.y));
        ((__nv_bfloat162*)g_Xh)[i * 2] = h0; ((__nv_bfloat162*)g_Xh)[i * 2 + 1] = h1;
        ((__nv_bfloat162*)g_Xl)[i * 2] = l0; ((__nv_bfloat162*)g_Xl)[i * 2 + 1] = l1;
    }
}

__global__ void prep_mats2(const float* __restrict__ Y1, const float* __restrict__ Chi,
                           const float* __restrict__ D12, const float* __restrict__ B2) {
    int idx = blockIdx.x * 256 + threadIdx.x;
    int i = idx >> 9, j = idx & 511;
    float h1 = g_H[(size_t)i * 1024 + j];
    g_RHS[(size_t)i * 1024 + j] =
        -0.5f * (h1 + ((i == j) ? EPSc : 0.0f) + Y1[(size_t)i * 512 + j] - Y1[(size_t)j * 512 + i]);
    g_RHS[(size_t)i * 1024 + 512 + j] =
        -g_H[(size_t)i * 1024 + 512 + j] - Chi[(size_t)i * 512 + j];
    float rl = 2.0f / (g_H[(size_t)(NXc + i) * 1024 + NXc + i] + EPSc);
    float d = (j < i) ? -g_H[(size_t)(512 + i) * 1024 + 512 + j] * rl : 0.0f;
    g_D11[(size_t)i * 512 + j] = d;
    g_D11p[(size_t)i * 512 + j] = __float2half_rn(d);
    float c1 = Chi[(size_t)j * 512 + i] * rl;
    g_C1p[(size_t)i * 512 + j] = __float2half_rn(c1);
    if (j < NUc) {
        g_D12p[(size_t)i * NUc + j] = __float2half_rn(D12[(size_t)i * NUc + j]);
        g_B2p[(size_t)i * NUc + j]  = __float2half_rn(B2[(size_t)i * NUc + j]);
    }
}

__global__ void reset_bar() { if (threadIdx.x == 0) g_barCnt = 0u; }

// ================= solver device pieces (fp32, 256 threads) =================
__device__ __forceinline__ void gbar(unsigned& gen) {
    __syncthreads();
    gen += 16;
    if (threadIdx.x == 0) {
        __threadfence();
        atomicAdd(&g_barCnt, 1u);
        while (*(volatile unsigned*)&g_barCnt < gen) { }
        __threadfence();
    }
    __syncthreads();
}

__device__ void dev_potf2_inv(int k, float (*S)[65], float* Dinv, float* sdp)
{
    int tid = threadIdx.x;
    for (int idx = tid; idx < 4096; idx += 256) {
        int i = idx >> 6, j = idx & 63;
        S[i][j] = g_P[(size_t)(k * 64 + i) * NXc + k * 64 + j];
    }
    __syncthreads();
    for (int j = 0; j < 64; ++j) {
        if (tid == 0) *sdp = rsqrtf(S[j][j]);
        __syncthreads();
        if (tid >= j && tid < 64) S[tid][j] *= *sdp;
        __syncthreads();
        for (int idx = tid; idx < 4096; idx += 256) {
            int i = idx >> 6, c = idx & 63;
            if (i > j && c > j) S[i][c] -= S[i][j] * S[c][j];
        }
        __syncthreads();
    }
    if (tid < 64) Dinv[tid] = 1.0f / S[tid][tid];
    __syncthreads();
    int wd = tid >> 5, lane = tid & 31;
    for (int cc = 0; cc < 8; ++cc) {
        int c = wd * 8 + cc;
        float x0 = (lane == c) ? 1.0f : 0.0f;
        float x1 = (lane + 32 == c) ? 1.0f : 0.0f;
        for (int i = c; i < 64; ++i) {
            float src = (i < 32) ? x0 : x1;
            float part = __shfl_sync(0xffffffffu, src, i & 31);
            float xv = part * Dinv[i];
            if (i < 32) { if (lane == i) x0 = xv; }
            else        { if (lane == i - 32) x1 = xv; }
            if (lane > i)      x0 -= S[lane][i] * xv;
            if (lane + 32 > i) x1 -= S[lane + 32][i] * xv;
        }
        g_Linv[k * 4096 + lane * 64 + c] = x0;
        g_Linv[k * 4096 + (lane + 32) * 64 + c] = x1;
    }
}

__device__ void dev_gemm_ABtK(const float* A, int lda, const float* B, int ldb,
                              float* C, int ldc, int K,
                              float alpha, float beta, float diagAdd,
                              float (*As)[68], float (*Bs)[68])
{
    int tid = threadIdx.x;
    int tx = tid & 15, ty = tid >> 4;
    float acc[4][4] = {};
    for (int kt = 0; kt < K; kt += 16) {
        __syncthreads();
        {
            int r = tid >> 2, kq = (tid & 3) * 4;
            float4 v = *(const float4*)(A + (size_t)r * lda + kt + kq);
            As[kq + 0][r] = v.x; As[kq + 1][r] = v.y; As[kq + 2][r] = v.z; As[kq + 3][r] = v.w;
            float4 w = *(const float4*)(B + (size_t)r * ldb + kt + kq);
            Bs[kq + 0][r] = w.x; Bs[kq + 1][r] = w.y; Bs[kq + 2][r] = w.z; Bs[kq + 3][r] = w.w;
        }
        __syncthreads();
        #pragma unroll
        for (int kk = 0; kk < 16; ++kk) {
            float4 a = *(const float4*)&As[kk][ty * 4];
            float4 b = *(const float4*)&Bs[kk][tx * 4];
            float am[4] = {a.x, a.y, a.z, a.w};
            float bm[4] = {b.x, b.y, b.z, b.w};
            #pragma unroll
            for (int i = 0; i < 4; ++i)
                #pragma unroll
                for (int j = 0; j < 4; ++j)
                    acc[i][j] += am[i] * bm[j];
        }
    }
    __syncthreads();
    #pragma unroll
    for (int i = 0; i < 4; ++i)
        #pragma unroll
        for (int j = 0; j < 4; ++j) {
            int li = ty * 4 + i, lj = tx * 4 + j;
            float v = alpha * acc[i][j];
            if (beta != 0.0f) v += beta * C[(size_t)li * ldc + lj];
            if (li == lj) v += diagAdd;
            C[(size_t)li * ldc + lj] = v;
        }
}

__device__ void dev_fwd(int c0, float (*Lt)[65], float (*Zt)[65])
{
    int tid = threadIdx.x;
    int tx = tid & 15, ty = tid >> 4;
    for (int ib = 0; ib < 8; ++ib) {
        float acc[4][4] = {};
        for (int jb = 0; jb < ib; ++jb) {
            for (int idx = tid; idx < 4096; idx += 256) {
                int i = idx >> 6, j = idx & 63;
                Lt[i][j] = g_P[(size_t)(ib * 64 + i) * 512 + jb * 64 + j];
                Zt[i][j] = g_Z[(size_t)(jb * 64 + i) * 1024 + c0 + j];
            }
            __syncthreads();
            #pragma unroll 8
            for (int kk = 0; kk < 64; ++kk)
                #pragma unroll
                for (int ii = 0; ii < 4; ++ii)
                    #pragma unroll
                    for (int jj = 0; jj < 4; ++jj)
                        acc[ii][jj] += Lt[ty * 4 + ii][kk] * Zt[kk][tx * 4 + jj];
            __syncthreads();
        }
        #pragma unroll
        for (int ii = 0; ii < 4; ++ii)
            #pragma unroll
            for (int jj = 0; jj < 4; ++jj)
                Zt[ty * 4 + ii][tx * 4 + jj] =
                    g_RHS[(size_t)(ib * 64 + ty * 4 + ii) * 1024 + c0 + tx * 4 + jj] - acc[ii][jj];
        for (int idx = tid; idx < 4096; idx += 256) {
            int i = idx >> 6, j = idx & 63;
            Lt[i][j] = g_Linv[ib * 4096 + i * 64 + j];
        }
        __syncthreads();
        float z[4][4] = {};
        #pragma unroll 8
        for (int kk = 0; kk < 64; ++kk)
            #pragma unroll
            for (int ii = 0; ii < 4; ++ii)
                #pragma unroll
                for (int jj = 0; jj < 4; ++jj)
                    z[ii][jj] += Lt[ty * 4 + ii][kk] * Zt[kk][tx * 4 + jj];
        #pragma unroll
        for (int ii = 0; ii < 4; ++ii)
            #pragma unroll
            for (int jj = 0; jj < 4; ++jj)
                g_Z[(size_t)(ib * 64 + ty * 4 + ii) * 1024 + c0 + tx * 4 + jj] = z[ii][jj];
        __syncthreads();
    }
}

__device__ void dev_bwd(int c0, float (*Lt)[65], float (*Zt)[65])
{
    int tid = threadIdx.x;
    int tx = tid & 15, ty = tid >> 4;
    for (int ib = 7; ib >= 0; --ib) {
        float acc[4][4] = {};
        for (int jb = ib + 1; jb < 8; ++jb) {
            for (int idx = tid; idx < 4096; idx += 256) {
                int i = idx >> 6, j = idx & 63;
                Lt[i][j] = g_P[(size_t)(jb * 64 + i) * 512 + ib * 64 + j];
                Zt[i][j] = g_S[(size_t)(jb * 64 + i) * 1024 + c0 + j];
            }
            __syncthreads();
            #pragma unroll 8
            for (int kk = 0; kk < 64; ++kk)
                #pragma unroll
                for (int ii = 0; ii < 4; ++ii)
                    #pragma unroll
                    for (int jj = 0; jj < 4; ++jj)
                        acc[ii][jj] += Lt[kk][ty * 4 + ii] * Zt[kk][tx * 4 + jj];
            __syncthreads();
        }
        #pragma unroll
        for (int ii = 0; ii < 4; ++ii)
            #pragma unroll
            for (int jj = 0; jj < 4; ++jj)
                Zt[ty * 4 + ii][tx * 4 + jj] =
                    g_Z[(size_t)(ib * 64 + ty * 4 + ii) * 1024 + c0 + tx * 4 + jj] - acc[ii][jj];
        for (int idx = tid; idx < 4096; idx += 256) {
            int i = idx >> 6, j = idx & 63;
            Lt[i][j] = g_Linv[ib * 4096 + i * 64 + j];
        }
        __syncthreads();
        float z[4][4] = {};
        #pragma unroll 8
        for (int kk = 0; kk < 64; ++kk)
            #pragma unroll
            for (int ii = 0; ii < 4; ++ii)
                #pragma unroll
                for (int jj = 0; jj < 4; ++jj)
                    z[ii][jj] += Lt[kk][ty * 4 + ii] * Zt[kk][tx * 4 + jj];
        #pragma unroll
        for (int ii = 0; ii < 4; ++ii)
            #pragma unroll
            for (int jj = 0; jj < 4; ++jj)
                g_S[(size_t)(ib * 64 + ty * 4 + ii) * 1024 + c0 + tx * 4 + jj] = z[ii][jj];
        __syncthreads();
    }
}

// ================= bf16 3-MMA GEMM (H only, unchanged) ======================
struct Seg {
    const __nv_bfloat16 *Ah, *Al, *Wh, *Wl;
    int lda, ldw, K;
};

template <int NT>
__global__ __launch_bounds__(512, 2) void mma_gemm(
    Seg s0, Seg s1, Seg s2, float* __restrict__ C, int ldc, int addTo)
{
    extern __shared__ __align__(128) char smem[];
    constexpr int AP  = 128 * 64;
    constexpr int WP  = NT * 64;
    constexpr int STG = 2 * AP + 2 * WP;
    constexpr int NAw = NT / 32;

    uint32_t sb = smem_to_u32(smem);
    int tid = threadIdx.x;
    int wid = tid >> 5, lane = tid & 31;
    int m0 = blockIdx.y * 128, n0 = blockIdx.x * NT;
    int wm = (wid & 3) * 32;
    int wn = (wid >> 2) * (NT / 4);

    int nk0 = s0.K >> 5, nk1 = s1.K >> 5, nk2 = s2.K >> 5;
    int nk = nk0 + nk1 + nk2;

    auto issue = [&](int c) {
        int cs = c;
        const Seg* sg = &s0;
        if (cs >= nk0) { cs -= nk0; sg = &s1; if (cs >= nk1) { cs -= nk1; sg = &s2; } }
        int kt = cs << 5;
        uint32_t stu = sb + (c & 1) * STG;
        #pragma unroll
        for (int s = tid; s < 1024; s += 512) {
            int pl = s >> 9, rem = s & 511, row = rem >> 2, q = rem & 3;
            const __nv_bfloat16* src =
                (pl ? sg->Al : sg->Ah) + (size_t)(m0 + row) * sg->lda + kt + q * 8;
            cpasync16(stu + pl * AP + swz64(row * 64 + q * 16), src);
        }
        #pragma unroll
        for (int s = tid; s < NT * 8; s += 512) {
            int pl = (s >= NT * 4) ? 1 : 0;
            int rem = pl ? s - NT * 4 : s;
            int row = rem >> 2, q = rem & 3;
            const __nv_bfloat16* src =
                (pl ? sg->Wl : sg->Wh) + (size_t)(n0 + row) * sg->ldw + kt + q * 8;
            cpasync16(stu + 2 * AP + pl * WP + swz64(row * 64 + q * 16), src);
        }
        CP_COMMIT();
    };

    float acc[2][NAw][4] = {};

    issue(0);
    for (int c = 0; c < nk; ++c) {
        if (c + 1 < nk) { issue(c + 1); CP_WAIT(1); }
        else            { CP_WAIT(0); }
        __syncthreads();
        uint32_t stu = sb + (c & 1) * STG;
        #pragma unroll
        for (int ks = 0; ks < 2; ++ks) {
            uint32_t ah[2][4], al[2][4];
            #pragma unroll
            for (int am = 0; am < 2; ++am) {
                uint32_t off = (uint32_t)(wm + am * 16 + (lane & 15)) * 64
                               + ks * 32 + (lane >> 4) * 16;
                ldsm4(ah[am], stu + swz64(off));
                ldsm4(al[am], stu + AP + swz64(off));
            }
            #pragma unroll
            for (int p = 0; p < NAw / 2; ++p) {
                int g = lane >> 3;
                uint32_t off = (uint32_t)(wn + p * 16 + ((g >> 1) << 3) + (lane & 7)) * 64
                               + ks * 32 + (g & 1) * 16;
                uint32_t th[4], tl[4];
                ldsm4(th, stu + 2 * AP + swz64(off));
                ldsm4(tl, stu + 2 * AP + WP + swz64(off));
                #pragma unroll
                for (int am = 0; am < 2; ++am) {
                    mma16816(acc[am][2 * p],     ah[am], th);
                    mma16816(acc[am][2 * p],     ah[am], tl);
                    mma16816(acc[am][2 * p],     al[am], th);
                    mma16816(acc[am][2 * p + 1], ah[am], th + 2);
                    mma16816(acc[am][2 * p + 1], ah[am], tl + 2);
                    mma16816(acc[am][2 * p + 1], al[am], th + 2);
                }
            }
        }
        __syncthreads();
    }

    #pragma unroll
    for (int am = 0; am < 2; ++am) {
        int r0 = m0 + wm + am * 16 + (lane >> 2);
        #pragma unroll
        for (int j = 0; j < NAw; ++j) {
            int cc = n0 + wn + j * 8 + (lane & 3) * 2;
            float* p0 = C + (size_t)r0 * ldc + cc;
            float* p1 = C + (size_t)(r0 + 8) * ldc + cc;
            float2 v0 = make_float2(acc[am][j][0], acc[am][j][1]);
            float2 v1 = make_float2(acc[am][j][2], acc[am][j][3]);
            if (addTo) {
                float2 o0 = *(const float2*)p0, o1 = *(const float2*)p1;
                v0.x += o0.x; v0.y += o0.y; v1.x += o1.x; v1.y += o1.y;
            }
            *(float2*)p0 = v0;
            *(float2*)p1 = v1;
        }
    }
}

// ============ fp16 single-MMA GEMM (out), K-chunk 64, SW128 =================
struct Seg3 {
    const __half *Ap, *Wp;
    int lda, ldw, K;
};

__global__ __launch_bounds__(512, 2) void mma_gemm_h(
    Seg3 s0, Seg3 s1, Seg3 s2, float* __restrict__ C, int ldc)
{
    extern __shared__ __align__(128) char smem[];
    constexpr int AP  = 128 * 128;  // single A plane per stage (128B rows)
    constexpr int WP  = 128 * 128;  // single W plane per stage
    constexpr int STG = AP + WP;    // 32768

    uint32_t sb = smem_to_u32(smem);
    int tid = threadIdx.x;
    int wid = tid >> 5, lane = tid & 31;
    int m0 = blockIdx.y * 128, n0 = blockIdx.x * 128;
    int wm = (wid & 3) * 32;
    int wn = (wid >> 2) * 32;

    int nk0 = s0.K >> 6, nk1 = s1.K >> 6, nk2 = s2.K >> 6;
    int nk = nk0 + nk1 + nk2;

    auto issue = [&](int c) {
        int cs = c;
        const Seg3* sg = &s0;
        if (cs >= nk0) { cs -= nk0; sg = &s1; if (cs >= nk1) { cs -= nk1; sg = &s2; } }
        int kt = cs << 6;
        uint32_t stu = sb + (c & 1) * STG;
        #pragma unroll
        for (int s = tid; s < 1024; s += 512) {
            int row = s >> 3, q = s & 7;
            const __half* src = sg->Ap + (size_t)(m0 + row) * sg->lda + kt + q * 8;
            cpasync16(stu + swz128(row * 128 + q * 16), src);
        }
        #pragma unroll
        for (int s = tid; s < 1024; s += 512) {
            int row = s >> 3, q = s & 7;
            const __half* src = sg->Wp + (size_t)(n0 + row) * sg->ldw + kt + q * 8;
            cpasync16(stu + AP + swz128(row * 128 + q * 16), src);
        }
        CP_COMMIT();
    };

    float acc[2][4][4] = {};

    issue(0);
    for (int c = 0; c < nk; ++c) {
        if (c + 1 < nk) { issue(c + 1); CP_WAIT(1); }
        else            { CP_WAIT(0); }
        __syncthreads();
        uint32_t stu = sb + (c & 1) * STG;
        #pragma unroll
        for (int ks = 0; ks < 4; ++ks) {
            uint32_t ah[2][4];
            #pragma unroll
            for (int am = 0; am < 2; ++am) {
                uint32_t off = (uint32_t)(wm + am * 16 + (lane & 15)) * 128
                               + ks * 32 + (lane >> 4) * 16;
                ldsm4(ah[am], stu + swz128(off));
            }
            #pragma unroll
            for (int p = 0; p < 2; ++p) {
                int g = lane >> 3;
                uint32_t off = (uint32_t)(wn + p * 16 + ((g >> 1) << 3) + (lane & 7)) * 128
                               + ks * 32 + (g & 1) * 16;
                uint32_t th[4];
                ldsm4(th, stu + AP + swz128(off));
                #pragma unroll
                for (int am = 0; am < 2; ++am) {
                    mma16816h(acc[am][2 * p],     ah[am], th);
                    mma16816h(acc[am][2 * p + 1], ah[am], th + 2);
                }
            }
        }
        __syncthreads();
    }

    #pragma unroll
    for (int am = 0; am < 2; ++am) {
        int r0 = m0 + wm + am * 16 + (lane >> 2);
        #pragma unroll
        for (int j = 0; j < 4; ++j) {
            int cc = n0 + wn + j * 8 + (lane & 3) * 2;
            *(float2*)(C + (size_t)r0 * ldc + cc) =
                make_float2(acc[am][j][0], acc[am][j][1]);
            *(float2*)(C + (size_t)(r0 + 8) * ldc + cc) =
                make_float2(acc[am][j][2], acc[am][j][3]);
        }
    }
}

// ==== fused base+cross GEMM (fp16 1-MMA, K-chunk 64) + scan + solver ========
__global__ __launch_bounds__(256) void scan_solve(const float* __restrict__ Pstar)
{
    extern __shared__ __align__(128) char smem[];
    int tid = threadIdx.x;

    if (blockIdx.x < 16) {
        float (*shA)[68] = (float(*)[68])(smem);
        float (*shB)[68] = (float(*)[68])(smem + 16 * 68 * 4);
        float (*S64)[65] = (float(*)[65])(smem + 2 * 16 * 68 * 4);
        float (*T64)[65] = (float(*)[65])(smem + 2 * 16 * 68 * 4 + 64 * 65 * 4);
        float* Dinv      = (float*)(smem + 2 * 16 * 68 * 4 + 2 * 64 * 65 * 4);
        float* sdv       = Dinv + 64;
        int cta = blockIdx.x;
        unsigned gen = 0;

        {
            int t = 0;
            for (int i = 0; i < 8; ++i)
                for (int j = 0; j <= i; ++j, ++t)
                    if ((t & 15) == cta)
                        dev_gemm_ABtK(Pstar + (size_t)i * 64 * 512, 512,
                                      Pstar + (size_t)j * 64 * 512, 512,
                                      g_P + (size_t)i * 64 * 512 + j * 64, 512,
                                      512, 0.5f, 0.0f, (i == j) ? EPSc : 0.0f,
                                      shA, shB);
            gbar(gen);
        }

        for (int k = 0; k < 8; ++k) {
            if (cta == 0) dev_potf2_inv(k, S64, Dinv, sdv);
            gbar(gen);
            int nrem = 7 - k;
            if (nrem > 0) {
                if (cta < nrem) {
                    int i = k + 1 + cta;
                    float* panel = g_P + (size_t)i * 64 * 512 + k * 64;
                    dev_gemm_ABtK(panel, 512, g_Linv + k * 4096, 64,
                                  panel, 512, 64, 1.0f, 0.0f, 0.0f, shA, shB);
                }
                gbar(gen);
                int t = 0;
                for (int i = k + 1; i < 8; ++i)
                    for (int j = k + 1; j <= i; ++j, ++t)
                        if ((t & 15) == cta)
                            dev_gemm_ABtK(g_P + (size_t)i * 64 * 512 + k * 64, 512,
                                          g_P + (size_t)j * 64 * 512 + k * 64, 512,
                                          g_P + (size_t)i * 64 * 512 + j * 64, 512,
                                          64, -1.0f, 1.0f, 0.0f, shA, shB);
                gbar(gen);
            }
        }
        dev_fwd(cta * 64, S64, T64);
        dev_bwd(cta * 64, S64, T64);
        gbar(gen);
        for (int i = cta * 256 + tid; i < NXc * 1024 / 4; i += 4096) {
            float4 v = ((const float4*)g_S)[i];
            __half2 h0, h1;
            h0.x = __float2half_rn(v.x); h0.y = __float2half_rn(v.y);
            h1.x = __float2half_rn(v.z); h1.y = __float2half_rn(v.w);
            ((__half2*)g_Sp)[i * 2] = h0; ((__half2*)g_Sp)[i * 2 + 1] = h1;
        }
        return;
    }

    constexpr int APc  = 128 * 128;           // single A plane stage (128B rows)
    constexpr int WPc  = 64 * 128;            // single W plane stage
    constexpr int STGc = APc + WPc;           // 24576
    constexpr int CRo  = 2 * STGc;            // 49152
    constexpr int DSo  = CRo + 128 * 68 * 4;  // 83968
    uint32_t sb = smem_to_u32(smem);
    float* cross = (float*)(smem + CRo);
    float* ds    = (float*)(smem + DSo);
    int wid = tid >> 5, lane = tid & 31;
    int strip0 = (blockIdx.x - 16) * 128;

    const __half* xiP = g_xip + (size_t)strip0 * NXc;
    const __half* uP  = g_up  + (size_t)strip0 * NUc;
    const __half* wP  = g_wp  + (size_t)strip0 * NQc;

    for (int b = 0; b < 8; ++b) {
        int nk = 10 + b;   // 8 (xi·C1, K=512) + 2 (u·D12, K=128) + b (w·D11, K=64b)

        auto issue = [&](int c) {
            int cs = c;
            const __half *Ap, *Wp;
            int lda, ldw;
            if (cs < 8) {
                Ap = xiP; lda = NXc;
                Wp = g_C1p + (size_t)b * 64 * NXc; ldw = NXc;
            } else if (cs < 10) {
                cs -= 8;
                Ap = uP; lda = NUc;
                Wp = g_D12p + (size_t)b * 64 * NUc; ldw = NUc;
            } else {
                cs -= 10;
                Ap = wP; lda = NQc;
                Wp = g_D11p + (size_t)b * 64 * NQc; ldw = NQc;
            }
            int kt = cs << 6;
            uint32_t stu = sb + (c & 1) * STGc;
            #pragma unroll
            for (int s = tid; s < 1024; s += 256) {
                int row = s >> 3, q = s & 7;
                const __half* src = Ap + (size_t)row * lda + kt + q * 8;
                cpasync16(stu + swz128(row * 128 + q * 16), src);
            }
            #pragma unroll
            for (int s = tid; s < 512; s += 256) {
                int row = s >> 3, q = s & 7;
                const __half* src = Wp + (size_t)row * ldw + kt + q * 8;
                cpasync16(stu + APc + swz128(row * 128 + q * 16), src);
            }
            CP_COMMIT();
        };

        float acc[2][4][4] = {};
        int wm = (wid & 3) * 32;
        int wn = (wid >> 2) * 32;

        issue(0);
        for (int c = 0; c < nk; ++c) {
            if (c + 1 < nk) { issue(c + 1); CP_WAIT(1); }
            else            { CP_WAIT(0); }
            __syncthreads();
            uint32_t stu = sb + (c & 1) * STGc;
            #pragma unroll
            for (int ks = 0; ks < 4; ++ks) {
                uint32_t ah[2][4];
                #pragma unroll
                for (int am = 0; am < 2; ++am) {
                    uint32_t off = (uint32_t)(wm + am * 16 + (lane & 15)) * 128
                                   + ks * 32 + (lane >> 4) * 16;
                    ldsm4(ah[am], stu + swz128(off));
                }
                #pragma unroll
                for (int p = 0; p < 2; ++p) {
                    int g = lane >> 3;
                    uint32_t off = (uint32_t)(wn + p * 16 + ((g >> 1) << 3) + (lane & 7)) * 128
                                   + ks * 32 + (g & 1) * 16;
                    uint32_t th[4];
                    ldsm4(th, stu + APc + swz128(off));
                    #pragma unroll
                    for (int am = 0; am < 2; ++am) {
                        mma16816h(acc[am][2 * p],     ah[am], th);
                        mma16816h(acc[am][2 * p + 1], ah[am], th + 2);
                    }
                }
            }
            __syncthreads();
        }

        #pragma unroll
        for (int am = 0; am < 2; ++am) {
            int r0 = wm + am * 16 + (lane >> 2);
            #pragma unroll
            for (int j = 0; j < 4; ++j) {
                int cc = wn + j * 8 + (lane & 3) * 2;
                cross[r0 * 68 + cc]           = acc[am][j][0];
                cross[r0 * 68 + cc + 1]       = acc[am][j][1];
                cross[(r0 + 8) * 68 + cc]     = acc[am][j][2];
                cross[(r0 + 8) * 68 + cc + 1] = acc[am][j][3];
            }
        }
        for (int idx = tid; idx < 4096; idx += 256) {
            int i = idx >> 6, j = idx & 63;
            ds[i * 65 + j] = g_D11[(size_t)(b * 64 + i) * NQc + b * 64 + j];
        }
        __syncthreads();

        if (tid < 128) {
            int r = strip0 + tid;
            float bb[64];
            #pragma unroll
            for (int q = 0; q < 64; ++q) bb[q] = cross[tid * 68 + q];
            float wv[64];
            #pragma unroll
            for (int i = 0; i < 64; ++i) {
                float s0 = 0.f, s1 = 0.f, s2 = 0.f, s3 = 0.f;
                #pragma unroll
                for (int j = 0; j < 64; ++j) {
                    if (j < i) {
                        float p = wv[j] * ds[i * 65 + j];
                        if      ((j & 3) == 0) s0 += p;
                        else if ((j & 3) == 1) s1 += p;
                        else if ((j & 3) == 2) s2 += p;
                        else                   s3 += p;
                    }
                }
                wv[i] = ftanh(bb[i] + ((s0 + s1) + (s2 + s3)));
            }
            __half2* wpp = (__half2*)(g_wp + (size_t)r * NQc + b * 64);
            #pragma unroll
            for (int q = 0; q < 32; ++q) {
                __half2 h;
                h.x = __float2half_rn(wv[q * 2]); h.y = __float2half_rn(wv[q * 2 + 1]);
                wpp[q] = h;
            }
        }
        __syncthreads();
    }
}

// ================= host orchestration =======================================
extern "C" void kernel_launch(void* const* d_in, const int* in_sizes, int n_in,
                              void* d_out, int out_size)
{
    const float* xi    = (const float*)d_in[1];
    const float* u     = (const float*)d_in[2];
    const float* Pstar = (const float*)d_in[3];
    const float* Chi   = (const float*)d_in[4];
    const float* Y1    = (const float*)d_in[5];
    const float* B2    = (const float*)d_in[6];
    const float* D12   = (const float*)d_in[7];
    const float* X     = (const float*)d_in[8];
    float* out = (float*)d_out;

    float* H;
    __half *xip, *up, *wp, *Sp, *B2p;
    __nv_bfloat16 *Xh, *Xl;
    cudaGetSymbolAddress((void**)&H, g_H);
    cudaGetSymbolAddress((void**)&xip, g_xip);
    cudaGetSymbolAddress((void**)&up, g_up);
    cudaGetSymbolAddress((void**)&wp, g_wp);
    cudaGetSymbolAddress((void**)&Xh, g_Xh);
    cudaGetSymbolAddress((void**)&Xl, g_Xl);
    cudaGetSymbolAddress((void**)&Sp, g_Sp);
    cudaGetSymbolAddress((void**)&B2p, g_B2p);

    constexpr int SM64  = 2 * (2 * 128 * 64 + 2 * 64 * 64);  // 49152 (bf16 H)
    constexpr int SMH   = 2 * (128 * 128 + 128 * 128);       // 65536 (fp16 out, Kc=64)
    constexpr int SMSF  = 2 * (128 * 128 + 64 * 128) + 128 * 68 * 4 + 64 * 65 * 4; // 100608
    cudaFuncSetAttribute(mma_gemm<64>, cudaFuncAttributeMaxDynamicSharedMemorySize, SM64);
    cudaFuncSetAttribute(mma_gemm_h,   cudaFuncAttributeMaxDynamicSharedMemorySize, SMH);
    cudaFuncSetAttribute(scan_solve,   cudaFuncAttributeMaxDynamicSharedMemorySize, SMSF);

    Seg zs = { nullptr, nullptr, nullptr, nullptr, 0, 0, 0 };

    // one launch: xi/u -> fp16 plane; X -> bf16 hi/lo
    split3<<<21504, 256>>>(xi, u, X);

    // H = X X^T via bf16 3-MMA (high precision, feeds inverse chain)
    Seg sXX = { Xh, Xl, Xh, Xl, 1024, 1024, 1024 };
    mma_gemm<64><<<dim3(16, 8), 512, SM64>>>(sXX, zs, zs, H, 1024, 0);

    // prep (RHS, D11(+fp16 plane), C1/D12/B2 fp16 planes)
    prep_mats2<<<1024, 256>>>(Y1, Chi, D12, B2);

    // fused: solver (16 CTAs: P + Cholesky + solves) || base+cross GEMM + scan
    reset_bar<<<1, 32>>>();
    scan_solve<<<272, 256, SMSF>>>(Pstar);

    // out = xi A^T + w B1^T + u B2^T  (fp16 single-MMA, Kc=64)
    Seg3 sXA = { xip, Sp, NXc, 1024, NXc };
    Seg3 sWB = { wp, Sp + 512, NQc, 1024, NQc };
    Seg3 sUB = { up, B2p, NUc, NUc, NUc };
    mma_gemm_h<<<dim3(4, 256), 512, SMH>>>(sXA, sWB, sUB, out, NXc);
}